// round 1
// baseline (speedup 1.0000x reference)
#include <cuda_runtime.h>
#include <math.h>

#define N 512
#define D 256
#define ROWS_PER_BLOCK 4

__device__ float g_norms[N];
__device__ float g_Ls[N];
__device__ int   g_perm[N];

// f = concat(features[:,0,:], features[:,1,:]) ; features is [256,2,256] row-major
__device__ __forceinline__ int fbase(int i){
  return (i < 256) ? (i * 512) : ((i - 256) * 512 + 256);
}

// ---------------- kernel 1: zero out, norms, global label bitonic sort ----------------
__global__ void __launch_bounds__(256) prep_kernel(const float* __restrict__ feat,
                                                   const float* __restrict__ labels,
                                                   float* __restrict__ out)
{
  int t = threadIdx.x;
  int lane = t & 31, w = t >> 5;
  if (t == 0) out[0] = 0.f;

  // squared norms of all 512 feature rows (warp-cooperative)
  for (int i = w; i < N; i += 8) {
    const float* fr = feat + fbase(i);
    float a = 0.f;
#pragma unroll
    for (int m = 0; m < 8; m++){ float v = fr[lane + 32*m]; a = fmaf(v, v, a); }
#pragma unroll
    for (int o = 16; o; o >>= 1) a += __shfl_xor_sync(0xffffffffu, a, o);
    if (lane == 0) g_norms[i] = a;
  }

  // bitonic sort of (label, original-row) pairs, 512 elements
  __shared__ float key[N];
  __shared__ int   idx[N];
  for (int r = t; r < N; r += 256){ key[r] = labels[r & 255]; idx[r] = r; }
  __syncthreads();
  for (int ksz = 2; ksz <= N; ksz <<= 1){
    for (int j = ksz >> 1; j > 0; j >>= 1){
      for (int r = t; r < N; r += 256){
        int p = r ^ j;
        if (p > r){
          bool up = ((r & ksz) == 0);
          float a = key[r], bv = key[p];
          bool sw = up ? (a > bv) : (a < bv);
          if (sw){ key[r] = bv; key[p] = a; int ti = idx[r]; idx[r] = idx[p]; idx[p] = ti; }
        }
      }
      __syncthreads();
    }
  }
  for (int r = t; r < N; r += 256){ g_Ls[r] = key[r]; g_perm[r] = idx[r]; }
}

// ---------------- kernel 2: distances + per-row loss ----------------
__global__ void __launch_bounds__(256, 1) rnc_kernel(const float* __restrict__ feat,
                                                     const float* __restrict__ labels,
                                                     float* __restrict__ out)
{
  __shared__ float  s_sq[ROWS_PER_BLOCK][N];
  __shared__ float  s_Ls[N];
  __shared__ int    s_perm[N];
  __shared__ float  s_es[N];
  __shared__ double s_P[N];
  __shared__ double s_acc;

  const int t = threadIdx.x, lane = t & 31, w = t >> 5;
  const int i0 = blockIdx.x * ROWS_PER_BLOCK;
  if (t == 0) s_acc = 0.0;
  for (int r = t; r < N; r += 256){ s_Ls[r] = g_Ls[r]; s_perm[r] = g_perm[r]; }

  // ---- phase A: squared distances for 4 rows via Gram trick, warp-per-column ----
  float fir[ROWS_PER_BLOCK][8], ni[ROWS_PER_BLOCK];
#pragma unroll
  for (int r = 0; r < ROWS_PER_BLOCK; r++){
    const float* fr = feat + fbase(i0 + r);
#pragma unroll
    for (int m = 0; m < 8; m++) fir[r][m] = fr[lane + 32*m];
    ni[r] = g_norms[i0 + r];
  }

  for (int j = w; j < N; j += 8){
    const float* fj = feat + fbase(j);
    float a0 = 0.f, a1 = 0.f, a2 = 0.f, a3 = 0.f;
#pragma unroll
    for (int m = 0; m < 8; m++){
      float v = fj[lane + 32*m];
      a0 = fmaf(fir[0][m], v, a0);
      a1 = fmaf(fir[1][m], v, a1);
      a2 = fmaf(fir[2][m], v, a2);
      a3 = fmaf(fir[3][m], v, a3);
    }
#pragma unroll
    for (int o = 16; o; o >>= 1){
      a0 += __shfl_xor_sync(0xffffffffu, a0, o);
      a1 += __shfl_xor_sync(0xffffffffu, a1, o);
      a2 += __shfl_xor_sync(0xffffffffu, a2, o);
      a3 += __shfl_xor_sync(0xffffffffu, a3, o);
    }
    if (lane == 0){
      float nj = g_norms[j];
      s_sq[0][j] = ni[0] + nj - 2.f * a0;
      s_sq[1][j] = ni[1] + nj - 2.f * a1;
      s_sq[2][j] = ni[2] + nj - 2.f * a2;
      s_sq[3][j] = ni[3] + nj - 2.f * a3;
    }
  }
  __syncthreads();

  // ---- phase B: per-row softmax denominators via sorted-label intervals ----
  double thread_acc = 0.0;

  for (int r = 0; r < ROWS_PER_BLOCK; r++){
    const int i = i0 + r;
    const float li = labels[i & 255];

    // exp row in sorted-label order; also accumulate sum of distances
    float dsum = 0.f;
    for (int x = t; x < N; x += 256){
      int j = s_perm[x];
      float e, d;
      if (j == i){ e = 1.f; d = 0.f; }       // diagonal: logit 0, exp 1
      else {
        float sq = s_sq[r][j];
        sq = sq > 0.f ? sq : 0.f;
        d = sqrtf(sq);
        e = expf(-0.5f * d);                 // exp(logit) with logits_max == 0, TEMP=2
      }
      s_es[x] = e;
      dsum += d;
    }
    __syncthreads();

    // inclusive prefix scan (double) over s_es, Hillis–Steele
    for (int x = t; x < N; x += 256) s_P[x] = (double)s_es[x];
    __syncthreads();
    for (int off = 1; off < N; off <<= 1){
      double v0 = 0.0, v1;
      int x0 = t, x1 = t + 256;
      if (x0 >= off) v0 = s_P[x0 - off];
      v1 = s_P[x1 - off];                    // x1 >= 256 >= off always
      __syncthreads();
      if (x0 >= off) s_P[x0] += v0;
      s_P[x1] += v1;
      __syncthreads();
    }
    const double total = s_P[N - 1];

    // per-k: neg = total - sum of exps whose label distance < t  (exact same fp compare as ref)
    double lsum = 0.0;
#pragma unroll
    for (int kk = 0; kk < 2; kk++){
      int k = t + kk * 256;
      if (k == i) continue;
      float lk = labels[k & 255];
      float tk = fabsf(lk - li);
      double neg;
      if (tk == 0.f){
        neg = total - 1.0;                   // all off-diag included; subtract exp_ii = 1
      } else {
        // il: first r with Ls[r] >= li (li appears in Ls)
        int lo = 0, len = N;
        while (len){ int h = len >> 1, m = lo + h;
          if (s_Ls[m] < li){ lo = m + 1; len -= h + 1; } else len = h; }
        int il = lo;
        // left boundary: first r in [0, il] with |Ls[r]-li| < tk (monotone, true at il)
        int a = 0, l2 = il + 1;
        while (l2){ int h = l2 >> 1, m = a + h;
          if (!(fabsf(s_Ls[m] - li) < tk)){ a = m + 1; l2 -= h + 1; } else l2 = h; }
        // right boundary: first r in [il, N) with |Ls[r]-li| >= tk
        int c = il, l3 = N - il;
        while (l3){ int h = l3 >> 1, m = c + h;
          if (fabsf(s_Ls[m] - li) < tk){ c = m + 1; l3 -= h + 1; } else l3 = h; }
        double interval = s_P[c - 1] - (a > 0 ? s_P[a - 1] : 0.0); // c > il >= 0
        neg = total - interval;              // interval contains exp_ii (dl=0 < tk)
      }
      lsum += (double)logf((float)neg);
    }

    thread_acc += 0.5 * (double)dsum + lsum; // dist/TEMP summed over all j (diag adds 0)
    __syncthreads();                          // protect s_es / s_P for next row
  }

  // block reduction and global accumulation
#pragma unroll
  for (int o = 16; o; o >>= 1)
    thread_acc += __shfl_xor_sync(0xffffffffu, thread_acc, o);
  if (lane == 0) atomicAdd(&s_acc, thread_acc);
  __syncthreads();
  if (t == 0){
    const double inv = 1.0 / (512.0 * 511.0); // 1 / (n*(n-1))
    atomicAdd(out, (float)(s_acc * inv));
  }
}

extern "C" void kernel_launch(void* const* d_in, const int* in_sizes, int n_in,
                              void* d_out, int out_size)
{
  const float* feat   = (const float*)d_in[0];   // [256, 2, 256] fp32
  const float* labels = (const float*)d_in[1];   // [256, 1] fp32
  float* out = (float*)d_out;                    // scalar fp32

  prep_kernel<<<1, 256>>>(feat, labels, out);
  rnc_kernel<<<N / ROWS_PER_BLOCK, 256>>>(feat, labels, out);
}

// round 2
// speedup vs baseline: 1.6270x; 1.6270x over previous
#include <cuda_runtime.h>
#include <math.h>

#define N 512

__device__ float g_Ls[N];      // labels duplicated & sorted
__device__ int   g_perm[N];    // sorted position -> original row
__device__ float g_d[N * N];   // pairwise L2 distances

// f = concat(features[:,0,:], features[:,1,:]) ; features is [256,2,256] row-major
__device__ __forceinline__ int fbase(int i){
  return (i < 256) ? (i * 512) : ((i - 256) * 512 + 256);
}

// ---------------- kernel 1: zero out + rank-sort labels (1 block) ----------------
__global__ void __launch_bounds__(256) prep_kernel(const float* __restrict__ labels,
                                                   float* __restrict__ out)
{
  const int t = threadIdx.x;
  __shared__ float sl[256];
  if (t == 0) out[0] = 0.f;
  sl[t] = labels[t];
  __syncthreads();
  const float v = sl[t];
  int r = 0;
#pragma unroll 8
  for (int j = 0; j < 256; j++){
    float u = sl[j];
    r += (u < v) | ((u == v) & (j < t));
  }
  g_Ls[2*r]     = v;  g_Ls[2*r + 1]   = v;
  g_perm[2*r]   = t;  g_perm[2*r + 1] = t + 256;
}

// ---------------- kernel 2: full distance matrix (128 blocks x 4 rows) ----------------
__global__ void __launch_bounds__(256, 1) dist_kernel(const float* __restrict__ feat)
{
  const int t = threadIdx.x, lane = t & 31, w = t >> 5;
  const int i0 = blockIdx.x * 4;

  float fir[4][8];
#pragma unroll
  for (int r = 0; r < 4; r++){
    const float* fr = feat + fbase(i0 + r);
#pragma unroll
    for (int m = 0; m < 8; m++) fir[r][m] = fr[lane + 32*m];
  }

  for (int j = w; j < N; j += 8){
    const float* fj = feat + fbase(j);
    float a0 = 0.f, a1 = 0.f, a2 = 0.f, a3 = 0.f;
#pragma unroll
    for (int m = 0; m < 8; m++){
      float v = fj[lane + 32*m];
      float t0 = fir[0][m] - v; a0 = fmaf(t0, t0, a0);
      float t1 = fir[1][m] - v; a1 = fmaf(t1, t1, a1);
      float t2 = fir[2][m] - v; a2 = fmaf(t2, t2, a2);
      float t3 = fir[3][m] - v; a3 = fmaf(t3, t3, a3);
    }
#pragma unroll
    for (int o = 16; o; o >>= 1){
      a0 += __shfl_xor_sync(0xffffffffu, a0, o);
      a1 += __shfl_xor_sync(0xffffffffu, a1, o);
      a2 += __shfl_xor_sync(0xffffffffu, a2, o);
      a3 += __shfl_xor_sync(0xffffffffu, a3, o);
    }
    if (lane == 0){
      g_d[(i0 + 0) * N + j] = sqrtf(a0);   // diagonal is exactly 0 (fi - fi == 0)
      g_d[(i0 + 1) * N + j] = sqrtf(a1);
      g_d[(i0 + 2) * N + j] = sqrtf(a2);
      g_d[(i0 + 3) * N + j] = sqrtf(a3);
    }
  }
}

// ---------------- kernel 3: per-row loss (512 blocks, one row each) ----------------
__global__ void __launch_bounds__(256) loss_kernel(const float* __restrict__ labels,
                                                   float* __restrict__ out)
{
  __shared__ float  s_Ls[N];
  __shared__ double s_P[N];       // inclusive prefix of exp in sorted order
  __shared__ double s_wsum[8];
  __shared__ double s_red[8];

  const int t = threadIdx.x, lane = t & 31, w = t >> 5;
  const int i = blockIdx.x;
  const float li = labels[i & 255];

  for (int x = t; x < N; x += 256) s_Ls[x] = g_Ls[x];

  // positions 2t, 2t+1 in sorted order: gather distance, exp
  const int x0 = 2*t, x1 = 2*t + 1;
  const int j0 = g_perm[x0], j1 = g_perm[x1];
  const float d0 = (j0 == i) ? 0.f : g_d[i * N + j0];
  const float d1 = (j1 == i) ? 0.f : g_d[i * N + j1];
  const float e0 = (j0 == i) ? 1.f : expf(-0.5f * d0);  // logits_max == 0, TEMP = 2
  const float e1 = (j1 == i) ? 1.f : expf(-0.5f * d1);

  // 2-barrier warp-shuffle inclusive scan over 512 exps
  double sc = (double)e0 + (double)e1;
#pragma unroll
  for (int o = 1; o < 32; o <<= 1){
    double v = __shfl_up_sync(0xffffffffu, sc, o);
    if (lane >= o) sc += v;
  }
  if (lane == 31) s_wsum[w] = sc;
  __syncthreads();
  if (w == 0 && lane < 8){
    double v = s_wsum[lane];
#pragma unroll
    for (int o = 1; o < 8; o <<= 1){
      double u = __shfl_up_sync(0xffu, v, o);
      if (lane >= o) v += u;
    }
    s_wsum[lane] = v;
  }
  __syncthreads();
  const double woff = (w > 0) ? s_wsum[w - 1] : 0.0;
  const double p1 = woff + sc;              // inclusive at x1
  s_P[x0] = p1 - (double)e1;                // inclusive at x0
  s_P[x1] = p1;
  __syncthreads();
  const double total = s_P[N - 1];

  // per-k: neg = total - sum of exps with label distance < tk (same fp compare as ref)
  double lsum = 0.0;
#pragma unroll
  for (int kk = 0; kk < 2; kk++){
    const int k = t + kk * 256;
    if (k == i) continue;
    const float lk = labels[k & 255];
    const float tk = fabsf(lk - li);
    double neg;
    if (tk == 0.f){
      neg = total - 1.0;                    // all off-diagonal included; remove exp_ii = 1
    } else {
      // il: first r with Ls[r] >= li
      int lo = 0, len = N;
      while (len){ int h = len >> 1, m = lo + h;
        if (s_Ls[m] < li){ lo = m + 1; len -= h + 1; } else len = h; }
      const int il = lo;
      // left boundary: first r in [0, il] with |Ls[r]-li| < tk
      int a = 0, l2 = il + 1;
      while (l2){ int h = l2 >> 1, m = a + h;
        if (!(fabsf(s_Ls[m] - li) < tk)){ a = m + 1; l2 -= h + 1; } else l2 = h; }
      // right boundary: first r in [il, N) with |Ls[r]-li| >= tk
      int c = il, l3 = N - il;
      while (l3){ int h = l3 >> 1, m = c + h;
        if (fabsf(s_Ls[m] - li) < tk){ c = m + 1; l3 -= h + 1; } else l3 = h; }
      const double interval = s_P[c - 1] - (a > 0 ? s_P[a - 1] : 0.0);
      neg = total - interval;               // interval contains exp_ii (0 < tk)
    }
    lsum += (double)logf((float)neg);
  }

  // loss contribution of this row: sum_j d_ij / TEMP + sum_k log(neg_ik)
  double acc = 0.5 * ((double)d0 + (double)d1) + lsum;

#pragma unroll
  for (int o = 16; o; o >>= 1)
    acc += __shfl_xor_sync(0xffffffffu, acc, o);
  if (lane == 0) s_red[w] = acc;
  __syncthreads();
  if (w == 0){
    double v = (lane < 8) ? s_red[lane] : 0.0;
#pragma unroll
    for (int o = 4; o; o >>= 1) v += __shfl_xor_sync(0xffffffffu, v, o);
    if (lane == 0){
      const double inv = 1.0 / (512.0 * 511.0);
      atomicAdd(out, (float)(v * inv));
    }
  }
}

extern "C" void kernel_launch(void* const* d_in, const int* in_sizes, int n_in,
                              void* d_out, int out_size)
{
  const float* feat   = (const float*)d_in[0];   // [256, 2, 256] fp32
  const float* labels = (const float*)d_in[1];   // [256, 1] fp32
  float* out = (float*)d_out;                    // scalar fp32

  prep_kernel<<<1, 256>>>(labels, out);
  dist_kernel<<<N / 4, 256>>>(feat);
  loss_kernel<<<N, 256>>>(labels, out);
}